// round 2
// baseline (speedup 1.0000x reference)
#include <cuda_runtime.h>
#include <math.h>

#define GH 160
#define GW 160
#define NPIX (GH*GW)
#define CCH 256
#define NA 9
#define NANCH (NPIX*NA)
#define TOPK 6000
#define NW 94
#define POSTK 300
#define GCAP 8192
#define IMG 2560.0f
#define STRIDE 16
#define DWHC ((float)4.135166556742356)
#define NMS_THR 0.7f
#define MINSZ 16.0f

// ---------- static scratch ----------
__device__ float              g_feat[CCH*NPIX];
__device__ float4             g_boxes[NANCH];
__device__ float              g_scores[NANCH];
__device__ unsigned           g_keys[NANCH];
__device__ unsigned           g_h1[65536];
__device__ unsigned           g_h2[65536];
__device__ unsigned           g_B, g_above, g_thr, g_gcnt;
__device__ unsigned long long g_gath[GCAP];
__device__ float4             g_tb[TOPK];
__device__ float              g_tarea[TOPK];
__device__ float              g_tsc[TOPK];
__device__ unsigned long long g_valid[NW];
__device__ unsigned long long g_mask[(size_t)TOPK*NW];
__device__ unsigned long long g_remv[NW];

// ---------- K0: clear ----------
__global__ void k_clear() {
    int i = blockIdx.x * 256 + threadIdx.x;   // grid 256 x 256 = 65536
    if (i < 65536) { g_h1[i] = 0u; g_h2[i] = 0u; }
    if (i < NW) g_valid[i] = 0ull;
    if (i == 0) g_gcnt = 0u;
}

// ---------- K1: 3x3 conv + ReLU ----------
__global__ __launch_bounds__(256, 2)
void k_conv(const float* __restrict__ in, const float* __restrict__ w,
            const float* __restrict__ bias) {
    __shared__ float sin_[4][34][35];
    __shared__ float sw[4][16][9];
    int tx = threadIdx.x, ty = threadIdx.y;
    int tid = ty * 16 + tx;
    int bx = blockIdx.x * 32, by = blockIdx.y * 32, cob = blockIdx.z * 16;

    float acc[16][2][2];
#pragma unroll
    for (int co = 0; co < 16; co++)
#pragma unroll
        for (int pr = 0; pr < 2; pr++)
#pragma unroll
            for (int ps = 0; ps < 2; ps++) acc[co][pr][ps] = 0.f;

    for (int ci0 = 0; ci0 < CCH; ci0 += 4) {
        __syncthreads();
        for (int t = tid; t < 34*34; t += 256) {
            int ly = t / 34, lx = t % 34;
            int gy = by + ly - 1, gx = bx + lx - 1;
            bool ok = (gy >= 0 && gy < GH && gx >= 0 && gx < GW);
#pragma unroll
            for (int c = 0; c < 4; c++)
                sin_[c][ly][lx] = ok ? in[(ci0 + c) * NPIX + gy * GW + gx] : 0.f;
        }
        for (int t = tid; t < 4*16*9; t += 256) {
            int c = t / 144, r = t % 144, co = r / 9, k = r % 9;
            sw[c][co][k] = w[(size_t)(cob + co) * (CCH*9) + (ci0 + c) * 9 + k];
        }
        __syncthreads();
#pragma unroll
        for (int c = 0; c < 4; c++) {
            float iv[4][4];
#pragma unroll
            for (int r = 0; r < 4; r++)
#pragma unroll
                for (int s = 0; s < 4; s++)
                    iv[r][s] = sin_[c][ty*2 + r][tx*2 + s];
#pragma unroll
            for (int co = 0; co < 16; co++) {
                float wv[9];
#pragma unroll
                for (int k = 0; k < 9; k++) wv[k] = sw[c][co][k];
#pragma unroll
                for (int pr = 0; pr < 2; pr++)
#pragma unroll
                    for (int ps = 0; ps < 2; ps++) {
                        float a0 = acc[co][pr][ps];
#pragma unroll
                        for (int ky = 0; ky < 3; ky++)
#pragma unroll
                            for (int kx = 0; kx < 3; kx++)
                                a0 = fmaf(wv[ky*3+kx], iv[pr+ky][ps+kx], a0);
                        acc[co][pr][ps] = a0;
                    }
            }
        }
    }
#pragma unroll
    for (int co = 0; co < 16; co++) {
        float bb = bias[cob + co];
#pragma unroll
        for (int pr = 0; pr < 2; pr++)
#pragma unroll
            for (int ps = 0; ps < 2; ps++) {
                int y = by + ty*2 + pr, x = bx + tx*2 + ps;
                g_feat[(cob + co) * NPIX + y * GW + x] = fmaxf(acc[co][pr][ps] + bb, 0.f);
            }
    }
}

// ---------- K2: heads + decode + sigmoid + key ----------
__global__ __launch_bounds__(128)
void k_heads(const float* __restrict__ cls_w, const float* __restrict__ cls_b,
             const float* __restrict__ bbox_w, const float* __restrict__ bbox_b) {
    __shared__ float ws[45][256];
    __shared__ float bs[45];
    int tid = threadIdx.x;
    for (int t = tid; t < 45*256; t += 128) {
        int j = t / 256, c = t % 256;
        ws[j][c] = (j < 9) ? cls_w[j*256 + c] : bbox_w[(j-9)*256 + c];
    }
    if (tid < 45) bs[tid] = (tid < 9) ? cls_b[tid] : bbox_b[tid - 9];
    __syncthreads();

    int pix = blockIdx.x * 128 + tid;
    float acc[45];
#pragma unroll
    for (int j = 0; j < 45; j++) acc[j] = 0.f;
    for (int c = 0; c < 256; c++) {
        float f = g_feat[c * NPIX + pix];
#pragma unroll
        for (int j = 0; j < 45; j++) acc[j] = fmaf(ws[j][c], f, acc[j]);
    }
#pragma unroll
    for (int j = 0; j < 45; j++) acc[j] += bs[j];

    int y = pix / GW, x = pix % GW;
    float fx = (float)(x * STRIDE), fy = (float)(y * STRIDE);
    const float ars[3] = {0.5f, 1.0f, 2.0f};
    const float scl[3] = {128.f, 256.f, 512.f};

#pragma unroll
    for (int a = 0; a < NA; a++) {
        int ai = a / 3, si = a % 3;
        float hr = sqrtf(ars[ai]);
        float wr = __fdiv_rn(1.0f, hr);
        float wsz = __fmul_rn(wr, scl[si]);
        float hsz = __fmul_rn(hr, scl[si]);
        float bx1 = rintf(__fmul_rn(-wsz, 0.5f));
        float bx2 = rintf(__fmul_rn( wsz, 0.5f));
        float by1 = rintf(__fmul_rn(-hsz, 0.5f));
        float by2 = rintf(__fmul_rn( hsz, 0.5f));
        float ax1 = __fadd_rn(fx, bx1), ax2 = __fadd_rn(fx, bx2);
        float ay1 = __fadd_rn(fy, by1), ay2 = __fadd_rn(fy, by2);
        float aw = __fsub_rn(ax2, ax1), ah = __fsub_rn(ay2, ay1);
        float cx = __fadd_rn(ax1, __fmul_rn(0.5f, aw));
        float cy = __fadd_rn(ay1, __fmul_rn(0.5f, ah));

        float score = __fdiv_rn(1.0f, __fadd_rn(1.0f, expf(-acc[a])));

        float dx = acc[9 + a*4 + 0];
        float dy = acc[9 + a*4 + 1];
        float dw = fminf(acc[9 + a*4 + 2], DWHC);
        float dh = fminf(acc[9 + a*4 + 3], DWHC);

        float pcx = __fadd_rn(__fmul_rn(dx, aw), cx);
        float pcy = __fadd_rn(__fmul_rn(dy, ah), cy);
        float pw  = __fmul_rn(expf(dw), aw);
        float ph  = __fmul_rn(expf(dh), ah);

        float x1 = __fsub_rn(pcx, __fmul_rn(0.5f, pw));
        float x2 = __fadd_rn(pcx, __fmul_rn(0.5f, pw));
        float y1 = __fsub_rn(pcy, __fmul_rn(0.5f, ph));
        float y2 = __fadd_rn(pcy, __fmul_rn(0.5f, ph));
        x1 = fminf(fmaxf(x1, 0.f), IMG);
        x2 = fminf(fmaxf(x2, 0.f), IMG);
        y1 = fminf(fmaxf(y1, 0.f), IMG);
        y2 = fminf(fmaxf(y2, 0.f), IMG);

        int idx = pix * NA + a;
        g_boxes[idx] = make_float4(x1, y1, x2, y2);
        g_scores[idx] = score;
        unsigned b = __float_as_uint(score);
        g_keys[idx] = b ^ ((b & 0x80000000u) ? 0xFFFFFFFFu : 0x80000000u);
    }
}

// ---------- radix select ----------
__global__ void k_hist1() {
    int i = blockIdx.x * 1024 + threadIdx.x;
    atomicAdd(&g_h1[g_keys[i] >> 16], 1u);
}

__global__ void k_scan1() {
    __shared__ unsigned cs[1024], pre[1024];
    int t = threadIdx.x;
    int hi = 65535 - t * 64;
    unsigned s = 0;
    for (int k = 0; k < 64; k++) s += g_h1[hi - k];
    cs[t] = s;
    __syncthreads();
    if (t == 0) { unsigned a = 0; for (int i = 0; i < 1024; i++) { pre[i] = a; a += cs[i]; } }
    __syncthreads();
    unsigned acc = pre[t];
    for (int k = 0; k < 64; k++) {
        unsigned b = hi - k, h = g_h1[b];
        if (acc < TOPK && acc + h >= TOPK) { g_B = b; g_above = acc; }
        acc += h;
    }
}

__global__ void k_hist2() {
    int i = blockIdx.x * 1024 + threadIdx.x;
    unsigned key = g_keys[i];
    if ((key >> 16) == g_B) atomicAdd(&g_h2[key & 0xFFFFu], 1u);
}

__global__ void k_scan2() {
    __shared__ unsigned cs[1024], pre[1024];
    int t = threadIdx.x;
    unsigned above = g_above, B = g_B;
    int hi = 65535 - t * 64;
    unsigned s = 0;
    for (int k = 0; k < 64; k++) s += g_h2[hi - k];
    cs[t] = s;
    __syncthreads();
    if (t == 0) { unsigned a = 0; for (int i = 0; i < 1024; i++) { pre[i] = a; a += cs[i]; } }
    __syncthreads();
    unsigned acc = pre[t] + above;
    for (int k = 0; k < 64; k++) {
        unsigned b = hi - k, h = g_h2[b];
        if (acc < TOPK && acc + h >= TOPK) g_thr = (B << 16) | b;
        acc += h;
    }
}

__global__ void k_gather() {
    int i = blockIdx.x * 1024 + threadIdx.x;
    unsigned key = g_keys[i];
    if (key >= g_thr) {
        unsigned p = atomicAdd(&g_gcnt, 1u);
        if (p < GCAP)
            g_gath[p] = ((unsigned long long)key << 32) | (unsigned)(~i);
    }
}

// ---------- bitonic sort (descending, 8192, one block) ----------
__global__ void k_sort() {
    int t = threadIdx.x;
    unsigned n = g_gcnt; if (n > GCAP) n = GCAP;
    for (int i = t; i < GCAP; i += 1024) if (i >= (int)n) g_gath[i] = 0ull;
    __syncthreads();
    for (int k = 2; k <= GCAP; k <<= 1) {
        for (int j = k >> 1; j > 0; j >>= 1) {
            for (int i = t; i < GCAP; i += 1024) {
                int x = i ^ j;
                if (x > i) {
                    unsigned long long a = g_gath[i], b = g_gath[x];
                    bool desc = ((i & k) == 0);
                    if ((a < b) == desc) { g_gath[i] = b; g_gath[x] = a; }
                }
            }
            __syncthreads();
        }
    }
}

// ---------- unpack top-6000 ----------
__global__ void k_post() {
    int i = blockIdx.x * 128 + threadIdx.x;
    if (i >= TOPK) return;
    unsigned long long kk = g_gath[i];
    unsigned idx = ~(unsigned)(kk & 0xFFFFFFFFull);
    float4 b = g_boxes[idx];
    g_tb[i] = b;
    float bw = __fsub_rn(b.z, b.x), bh = __fsub_rn(b.w, b.y);
    g_tarea[i] = __fmul_rn(bw, bh);
    g_tsc[i] = g_scores[idx];
    if (bw >= MINSZ && bh >= MINSZ)
        atomicOr(&g_valid[i >> 6], 1ull << (i & 63));
}

// ---------- NMS mask ----------
__global__ void k_mask() {
    int bi = blockIdx.y, bj = blockIdx.x;
    __shared__ float4 cb[64];
    __shared__ float  ca[64];
    int jb = bj * 64;
    int nc = min(64, TOPK - jb);
    int t = threadIdx.x;
    if (t < nc) { cb[t] = g_tb[jb + t]; ca[t] = g_tarea[jb + t]; }
    __syncthreads();
    int i = bi * 64 + t;
    if (i >= TOPK) return;
    unsigned long long w = 0ull;
    if (bj >= bi) {
        float4 b = g_tb[i];
        float ai = g_tarea[i];
        for (int c = 0; c < nc; c++) {
            int j = jb + c;
            if (j <= i) continue;
            float4 o = cb[c];
            float xl = fmaxf(b.x, o.x), yt = fmaxf(b.y, o.y);
            float xr = fminf(b.z, o.z), yb = fminf(b.w, o.w);
            float iw = fmaxf(__fsub_rn(xr, xl), 0.f);
            float ih = fmaxf(__fsub_rn(yb, yt), 0.f);
            float inter = __fmul_rn(iw, ih);
            float iou = __fdiv_rn(inter, __fsub_rn(__fadd_rn(ai, ca[c]), inter));
            if (iou > NMS_THR) w |= 1ull << c;
        }
    }
    g_mask[(size_t)i * NW + bj] = w;
}

// ---------- NMS sequential reduce (chunked) ----------
__global__ void k_reduce() {
    __shared__ unsigned long long remv[NW];
    __shared__ unsigned long long diag[64];
    __shared__ unsigned long long cur;
    int t = threadIdx.x;
    if (t < NW) remv[t] = 0ull;
    __syncthreads();
    for (int cw = 0; cw < NW; cw++) {
        int base = cw * 64;
        int nr = min(64, TOPK - base);
        for (int b = t; b < nr; b += 128) diag[b] = g_mask[(size_t)(base + b) * NW + cw];
        __syncthreads();
        if (t == 0) {
            unsigned long long rem = remv[cw] | ~g_valid[cw];
            for (int b = 0; b < nr; b++)
                if (!((rem >> b) & 1ull)) rem |= diag[b];
            remv[cw] = rem; cur = rem;
        }
        __syncthreads();
        unsigned long long rem = cur;
        if (t < NW && t > cw) {
            for (int b = 0; b < nr; b++)
                if (!((rem >> b) & 1ull))
                    remv[t] |= g_mask[(size_t)(base + b) * NW + t];
        }
        __syncthreads();
    }
    if (t < NW) g_remv[t] = remv[t];
}

// ---------- emit top-300 ----------
__global__ void k_out(float* __restrict__ out) {
    unsigned long long keep[NW];
    for (int w = 0; w < NW; w++) keep[w] = ~g_remv[w];   // g_remv already includes invalid
    int cnt = 0;
    for (int i = 0; i < TOPK && cnt < POSTK; i++) {
        if ((keep[i >> 6] >> (i & 63)) & 1ull) {
            float4 b = g_tb[i];
            out[cnt*5+0] = b.x; out[cnt*5+1] = b.y;
            out[cnt*5+2] = b.z; out[cnt*5+3] = b.w;
            out[cnt*5+4] = g_tsc[i];
            cnt++;
        }
    }
    for (int i = 0; i < TOPK && cnt < POSTK; i++) {
        if (!((keep[i >> 6] >> (i & 63)) & 1ull)) {
            float4 b = g_tb[i];
            out[cnt*5+0] = b.x; out[cnt*5+1] = b.y;
            out[cnt*5+2] = b.z; out[cnt*5+3] = b.w;
            out[cnt*5+4] = -1.0f;
            cnt++;
        }
    }
}

extern "C" void kernel_launch(void* const* d_in, const int* in_sizes, int n_in,
                              void* d_out, int out_size) {
    const float* feat   = (const float*)d_in[0];
    const float* conv_w = (const float*)d_in[2];
    const float* conv_b = (const float*)d_in[3];
    const float* cls_w  = (const float*)d_in[4];
    const float* cls_b  = (const float*)d_in[5];
    const float* bbox_w = (const float*)d_in[6];
    const float* bbox_b = (const float*)d_in[7];
    float* out = (float*)d_out;

    k_clear<<<256, 256>>>();
    k_conv<<<dim3(5, 5, 16), dim3(16, 16)>>>(feat, conv_w, conv_b);
    k_heads<<<200, 128>>>(cls_w, cls_b, bbox_w, bbox_b);
    k_hist1<<<225, 1024>>>();
    k_scan1<<<1, 1024>>>();
    k_hist2<<<225, 1024>>>();
    k_scan2<<<1, 1024>>>();
    k_gather<<<225, 1024>>>();
    k_sort<<<1, 1024>>>();
    k_post<<<47, 128>>>();
    k_mask<<<dim3(94, 94), 64>>>();
    k_reduce<<<1, 128>>>();
    k_out<<<1, 1>>>(out);
}

// round 3
// speedup vs baseline: 1.0117x; 1.0117x over previous
#include <cuda_runtime.h>
#include <math.h>

#define GH 160
#define GW 160
#define NPIX (GH*GW)
#define CCH 256
#define NA 9
#define NANCH (NPIX*NA)
#define TOPK 6000
#define NW 94
#define POSTK 300
#define GCAP 8192
#define IMG 2560.0f
#define STRIDE 16
#define DWHC ((float)4.135166556742356)
#define NMS_THR 0.7f
#define MINSZ 16.0f

// ---------- static scratch ----------
__device__ float              g_feat[CCH*NPIX];
__device__ float4             g_boxes[NANCH];
__device__ float              g_scores[NANCH];
__device__ unsigned           g_keys[NANCH];
__device__ unsigned           g_h1[65536];
__device__ unsigned           g_h2[65536];
__device__ unsigned           g_B, g_above, g_thr, g_gcnt;
__device__ unsigned long long g_gath[GCAP];
__device__ float4             g_tb[TOPK];
__device__ float              g_tarea[TOPK];
__device__ float              g_tsc[TOPK];
__device__ unsigned long long g_valid[NW];
__device__ unsigned long long g_mask[(size_t)TOPK*NW];
__device__ unsigned long long g_remv[NW];

// ---------- f32x2 helpers ----------
__device__ __forceinline__ unsigned long long pk2(float lo, float hi) {
    unsigned long long r;
    asm("mov.b64 %0, {%1, %2};" : "=l"(r) : "f"(lo), "f"(hi));
    return r;
}
__device__ __forceinline__ void upk2(unsigned long long v, float& lo, float& hi) {
    asm("mov.b64 {%0, %1}, %2;" : "=f"(lo), "=f"(hi) : "l"(v));
}
__device__ __forceinline__ void ffma2(unsigned long long& c,
                                      unsigned long long a, unsigned long long b) {
    asm("fma.rn.f32x2 %0, %1, %2, %0;" : "+l"(c) : "l"(a), "l"(b));
}

// ---------- K0: clear ----------
__global__ void k_clear() {
    int i = blockIdx.x * 256 + threadIdx.x;   // 256 x 256 = 65536
    if (i < 65536) { g_h1[i] = 0u; g_h2[i] = 0u; }
    if (i < NW) g_valid[i] = 0ull;
    if (i == 0) g_gcnt = 0u;
}

// ---------- K1: 3x3 conv + ReLU (FFMA2 packed over x-pixel pair) ----------
// block (16,16): 32x32 spatial tile, 8 output channels, 2x2 px/thread
__global__ __launch_bounds__(256, 2)
void k_conv(const float* __restrict__ in, const float* __restrict__ w,
            const float* __restrict__ bias) {
    __shared__ float sin_[4][34][35];
    __shared__ float sw2[4][8][9][2];   // duplicated weights -> aligned LDS.64 of (w,w)
    int tx = threadIdx.x, ty = threadIdx.y;
    int tid = ty * 16 + tx;
    int bx = blockIdx.x * 32, by = blockIdx.y * 32, cob = blockIdx.z * 8;

    unsigned long long acc[8][2];   // [co][pr], packed over ps pair
#pragma unroll
    for (int co = 0; co < 8; co++) { acc[co][0] = 0ull; acc[co][1] = 0ull; }

    for (int ci0 = 0; ci0 < CCH; ci0 += 4) {
        __syncthreads();
        for (int t = tid; t < 34*34; t += 256) {
            int ly = t / 34, lx = t % 34;
            int gy = by + ly - 1, gx = bx + lx - 1;
            bool ok = (gy >= 0 && gy < GH && gx >= 0 && gx < GW);
#pragma unroll
            for (int c = 0; c < 4; c++)
                sin_[c][ly][lx] = ok ? in[(ci0 + c) * NPIX + gy * GW + gx] : 0.f;
        }
        for (int t = tid; t < 4*8*9; t += 256) {
            int c = t / 72, r = t % 72, co = r / 9, k = r % 9;
            float wv = w[(size_t)(cob + co) * (CCH*9) + (ci0 + c) * 9 + k];
            sw2[c][co][k][0] = wv;
            sw2[c][co][k][1] = wv;
        }
        __syncthreads();
#pragma unroll
        for (int c = 0; c < 4; c++) {
            float iv[4][4];
#pragma unroll
            for (int r = 0; r < 4; r++)
#pragma unroll
                for (int s = 0; s < 4; s++)
                    iv[r][s] = sin_[c][ty*2 + r][tx*2 + s];
            unsigned long long iv2[4][3];
#pragma unroll
            for (int r = 0; r < 4; r++)
#pragma unroll
                for (int kx = 0; kx < 3; kx++)
                    iv2[r][kx] = pk2(iv[r][kx], iv[r][kx+1]);
#pragma unroll
            for (int co = 0; co < 8; co++) {
#pragma unroll
                for (int ky = 0; ky < 3; ky++)
#pragma unroll
                    for (int kx = 0; kx < 3; kx++) {
                        unsigned long long w2 =
                            *reinterpret_cast<const unsigned long long*>(&sw2[c][co][ky*3+kx][0]);
                        ffma2(acc[co][0], iv2[ky + 0][kx], w2);
                        ffma2(acc[co][1], iv2[ky + 1][kx], w2);
                    }
            }
        }
    }
#pragma unroll
    for (int co = 0; co < 8; co++) {
        float bb = bias[cob + co];
#pragma unroll
        for (int pr = 0; pr < 2; pr++) {
            float lo, hi;
            upk2(acc[co][pr], lo, hi);
            int y = by + ty*2 + pr, x = bx + tx*2;
            g_feat[(cob + co) * NPIX + y * GW + x + 0] = fmaxf(lo + bb, 0.f);
            g_feat[(cob + co) * NPIX + y * GW + x + 1] = fmaxf(hi + bb, 0.f);
        }
    }
}

// ---------- K2: heads + decode + sigmoid + key ----------
__global__ __launch_bounds__(128)
void k_heads(const float* __restrict__ cls_w, const float* __restrict__ cls_b,
             const float* __restrict__ bbox_w, const float* __restrict__ bbox_b) {
    __shared__ float ws[45][256];
    __shared__ float bs[45];
    int tid = threadIdx.x;
    for (int t = tid; t < 45*256; t += 128) {
        int j = t / 256, c = t % 256;
        ws[j][c] = (j < 9) ? cls_w[j*256 + c] : bbox_w[(j-9)*256 + c];
    }
    if (tid < 45) bs[tid] = (tid < 9) ? cls_b[tid] : bbox_b[tid - 9];
    __syncthreads();

    int pix = blockIdx.x * 128 + tid;
    float acc[45];
#pragma unroll
    for (int j = 0; j < 45; j++) acc[j] = 0.f;
    for (int c = 0; c < 256; c++) {
        float f = g_feat[c * NPIX + pix];
#pragma unroll
        for (int j = 0; j < 45; j++) acc[j] = fmaf(ws[j][c], f, acc[j]);
    }
#pragma unroll
    for (int j = 0; j < 45; j++) acc[j] += bs[j];

    int y = pix / GW, x = pix % GW;
    float fx = (float)(x * STRIDE), fy = (float)(y * STRIDE);
    const float ars[3] = {0.5f, 1.0f, 2.0f};
    const float scl[3] = {128.f, 256.f, 512.f};

#pragma unroll
    for (int a = 0; a < NA; a++) {
        int ai = a / 3, si = a % 3;
        float hr = sqrtf(ars[ai]);
        float wr = __fdiv_rn(1.0f, hr);
        float wsz = __fmul_rn(wr, scl[si]);
        float hsz = __fmul_rn(hr, scl[si]);
        float bx1 = rintf(__fmul_rn(-wsz, 0.5f));
        float bx2 = rintf(__fmul_rn( wsz, 0.5f));
        float by1 = rintf(__fmul_rn(-hsz, 0.5f));
        float by2 = rintf(__fmul_rn( hsz, 0.5f));
        float ax1 = __fadd_rn(fx, bx1), ax2 = __fadd_rn(fx, bx2);
        float ay1 = __fadd_rn(fy, by1), ay2 = __fadd_rn(fy, by2);
        float aw = __fsub_rn(ax2, ax1), ah = __fsub_rn(ay2, ay1);
        float cx = __fadd_rn(ax1, __fmul_rn(0.5f, aw));
        float cy = __fadd_rn(ay1, __fmul_rn(0.5f, ah));

        float score = __fdiv_rn(1.0f, __fadd_rn(1.0f, expf(-acc[a])));

        float dx = acc[9 + a*4 + 0];
        float dy = acc[9 + a*4 + 1];
        float dw = fminf(acc[9 + a*4 + 2], DWHC);
        float dh = fminf(acc[9 + a*4 + 3], DWHC);

        float pcx = __fadd_rn(__fmul_rn(dx, aw), cx);
        float pcy = __fadd_rn(__fmul_rn(dy, ah), cy);
        float pw  = __fmul_rn(expf(dw), aw);
        float ph  = __fmul_rn(expf(dh), ah);

        float x1 = __fsub_rn(pcx, __fmul_rn(0.5f, pw));
        float x2 = __fadd_rn(pcx, __fmul_rn(0.5f, pw));
        float y1 = __fsub_rn(pcy, __fmul_rn(0.5f, ph));
        float y2 = __fadd_rn(pcy, __fmul_rn(0.5f, ph));
        x1 = fminf(fmaxf(x1, 0.f), IMG);
        x2 = fminf(fmaxf(x2, 0.f), IMG);
        y1 = fminf(fmaxf(y1, 0.f), IMG);
        y2 = fminf(fmaxf(y2, 0.f), IMG);

        int idx = pix * NA + a;
        g_boxes[idx] = make_float4(x1, y1, x2, y2);
        g_scores[idx] = score;
        unsigned b = __float_as_uint(score);
        g_keys[idx] = b ^ ((b & 0x80000000u) ? 0xFFFFFFFFu : 0x80000000u);
    }
}

// ---------- radix select ----------
__global__ void k_hist1() {
    int i = blockIdx.x * 1024 + threadIdx.x;
    atomicAdd(&g_h1[g_keys[i] >> 16], 1u);
}

__global__ void k_scan1() {
    __shared__ unsigned cs[1024], pre[1024];
    int t = threadIdx.x;
    int hi = 65535 - t * 64;
    unsigned s = 0;
    for (int k = 0; k < 64; k++) s += g_h1[hi - k];
    cs[t] = s;
    __syncthreads();
    if (t == 0) { unsigned a = 0; for (int i = 0; i < 1024; i++) { pre[i] = a; a += cs[i]; } }
    __syncthreads();
    unsigned acc = pre[t];
    for (int k = 0; k < 64; k++) {
        unsigned b = hi - k, h = g_h1[b];
        if (acc < TOPK && acc + h >= TOPK) { g_B = b; g_above = acc; }
        acc += h;
    }
}

__global__ void k_hist2() {
    int i = blockIdx.x * 1024 + threadIdx.x;
    unsigned key = g_keys[i];
    if ((key >> 16) == g_B) atomicAdd(&g_h2[key & 0xFFFFu], 1u);
}

__global__ void k_scan2() {
    __shared__ unsigned cs[1024], pre[1024];
    int t = threadIdx.x;
    unsigned above = g_above, B = g_B;
    int hi = 65535 - t * 64;
    unsigned s = 0;
    for (int k = 0; k < 64; k++) s += g_h2[hi - k];
    cs[t] = s;
    __syncthreads();
    if (t == 0) { unsigned a = 0; for (int i = 0; i < 1024; i++) { pre[i] = a; a += cs[i]; } }
    __syncthreads();
    unsigned acc = pre[t] + above;
    for (int k = 0; k < 64; k++) {
        unsigned b = hi - k, h = g_h2[b];
        if (acc < TOPK && acc + h >= TOPK) g_thr = (B << 16) | b;
        acc += h;
    }
}

__global__ void k_gather() {
    int i = blockIdx.x * 1024 + threadIdx.x;
    unsigned key = g_keys[i];
    if (key >= g_thr) {
        unsigned p = atomicAdd(&g_gcnt, 1u);
        if (p < GCAP)
            g_gath[p] = ((unsigned long long)key << 32) | (unsigned)(~i);
    }
}

// ---------- bitonic sort in shared memory (descending, 8192, one block) ----------
__global__ void k_sort() {
    extern __shared__ unsigned long long s[];
    int t = threadIdx.x;
    unsigned n = g_gcnt; if (n > GCAP) n = GCAP;
    for (int i = t; i < GCAP; i += 1024)
        s[i] = (i < (int)n) ? g_gath[i] : 0ull;
    __syncthreads();
    for (int k = 2; k <= GCAP; k <<= 1) {
        for (int j = k >> 1; j > 0; j >>= 1) {
            for (int p = t; p < GCAP/2; p += 1024) {
                int i = ((p / j) * 2 * j) + (p % j);
                int x = i + j;
                unsigned long long a = s[i], b = s[x];
                bool desc = ((i & k) == 0);
                if ((a < b) == desc) { s[i] = b; s[x] = a; }
            }
            __syncthreads();
        }
    }
    for (int i = t; i < TOPK; i += 1024) g_gath[i] = s[i];
}

// ---------- unpack top-6000 ----------
__global__ void k_post() {
    int i = blockIdx.x * 128 + threadIdx.x;
    if (i >= TOPK) return;
    unsigned long long kk = g_gath[i];
    unsigned idx = ~(unsigned)(kk & 0xFFFFFFFFull);
    float4 b = g_boxes[idx];
    g_tb[i] = b;
    float bw = __fsub_rn(b.z, b.x), bh = __fsub_rn(b.w, b.y);
    g_tarea[i] = __fmul_rn(bw, bh);
    g_tsc[i] = g_scores[idx];
    if (bw >= MINSZ && bh >= MINSZ)
        atomicOr(&g_valid[i >> 6], 1ull << (i & 63));
}

// ---------- NMS mask ----------
__global__ void k_mask() {
    int bi = blockIdx.y, bj = blockIdx.x;
    __shared__ float4 cb[64];
    __shared__ float  ca[64];
    int jb = bj * 64;
    int nc = min(64, TOPK - jb);
    int t = threadIdx.x;
    if (t < nc) { cb[t] = g_tb[jb + t]; ca[t] = g_tarea[jb + t]; }
    __syncthreads();
    int i = bi * 64 + t;
    if (i >= TOPK) return;
    unsigned long long w = 0ull;
    if (bj >= bi) {
        float4 b = g_tb[i];
        float ai = g_tarea[i];
        for (int c = 0; c < nc; c++) {
            int j = jb + c;
            if (j <= i) continue;
            float4 o = cb[c];
            float xl = fmaxf(b.x, o.x), yt = fmaxf(b.y, o.y);
            float xr = fminf(b.z, o.z), yb = fminf(b.w, o.w);
            float iw = fmaxf(__fsub_rn(xr, xl), 0.f);
            float ih = fmaxf(__fsub_rn(yb, yt), 0.f);
            float inter = __fmul_rn(iw, ih);
            float iou = __fdiv_rn(inter, __fsub_rn(__fadd_rn(ai, ca[c]), inter));
            if (iou > NMS_THR) w |= 1ull << c;
        }
    }
    g_mask[(size_t)i * NW + bj] = w;
}

// ---------- NMS sequential reduce (smem-staged stripes) ----------
__global__ void k_reduce() {
    __shared__ unsigned long long st[64][NW];   // 48128 B stripe
    __shared__ unsigned long long remv[NW];
    __shared__ unsigned long long cur;
    int t = threadIdx.x;
    if (t < NW) remv[t] = 0ull;
    __syncthreads();
    for (int cw = 0; cw < NW; cw++) {
        int base = cw * 64;
        int nr = min(64, TOPK - base);
        for (int idx = t; idx < nr * NW; idx += 128) {
            int r = idx / NW, wd = idx % NW;
            st[r][wd] = g_mask[(size_t)(base + r) * NW + wd];
        }
        __syncthreads();
        if (t == 0) {
            unsigned long long rem = remv[cw] | ~g_valid[cw];
            for (int b = 0; b < nr; b++)
                if (!((rem >> b) & 1ull)) rem |= st[b][cw];
            remv[cw] = rem; cur = rem;
        }
        __syncthreads();
        unsigned long long rem = cur;
        if (t < NW && t > cw) {
            unsigned long long acc = remv[t];
            for (int b = 0; b < nr; b++)
                if (!((rem >> b) & 1ull)) acc |= st[b][t];
            remv[t] = acc;
        }
        __syncthreads();
    }
    if (t < NW) g_remv[t] = remv[t];
}

// ---------- emit top-300 (parallel rank) ----------
__global__ void k_out(float* __restrict__ out) {
    __shared__ unsigned long long keep[NW];
    __shared__ int ks[NW], ns[NW];
    __shared__ int Kc;
    int t = threadIdx.x;
    if (t < NW) {
        unsigned long long k = ~g_remv[t];
        if (t == NW - 1) k &= (1ull << 48) - 1ull;   // 6000 = 93*64+48
        keep[t] = k;
    }
    __syncthreads();
    if (t == 0) {
        int a = 0, b = 0;
        for (int w = 0; w < NW; w++) {
            ks[w] = a; ns[w] = b;
            int nb = (w == NW - 1) ? 48 : 64;
            int p = __popcll(keep[w]);
            a += p; b += nb - p;
        }
        Kc = min(a, POSTK);
    }
    __syncthreads();
    int kc = Kc;
    for (int i = t; i < TOPK; i += 128) {
        int w = i >> 6, b = i & 63;
        unsigned long long kw = keep[w];
        unsigned long long pm = (b == 0) ? 0ull : (kw << (64 - b)) >> (64 - b);
        // pm = kw & ((1<<b)-1) without UB at b==0
        pm = kw & ((b == 0) ? 0ull : ((1ull << b) - 1ull));
        bool isk = (kw >> b) & 1ull;
        int pos;
        if (isk) {
            pos = ks[w] + __popcll(pm);
            if (pos < POSTK) {
                float4 bb = g_tb[i];
                out[pos*5+0] = bb.x; out[pos*5+1] = bb.y;
                out[pos*5+2] = bb.z; out[pos*5+3] = bb.w;
                out[pos*5+4] = g_tsc[i];
            }
        } else {
            unsigned long long nm = (~kw) & ((b == 0) ? 0ull : ((1ull << b) - 1ull));
            pos = kc + ns[w] + __popcll(nm);
            if (pos < POSTK) {
                float4 bb = g_tb[i];
                out[pos*5+0] = bb.x; out[pos*5+1] = bb.y;
                out[pos*5+2] = bb.z; out[pos*5+3] = bb.w;
                out[pos*5+4] = -1.0f;
            }
        }
    }
}

extern "C" void kernel_launch(void* const* d_in, const int* in_sizes, int n_in,
                              void* d_out, int out_size) {
    const float* feat   = (const float*)d_in[0];
    const float* conv_w = (const float*)d_in[2];
    const float* conv_b = (const float*)d_in[3];
    const float* cls_w  = (const float*)d_in[4];
    const float* cls_b  = (const float*)d_in[5];
    const float* bbox_w = (const float*)d_in[6];
    const float* bbox_b = (const float*)d_in[7];
    float* out = (float*)d_out;

    cudaFuncSetAttribute(k_sort, cudaFuncAttributeMaxDynamicSharedMemorySize,
                         GCAP * sizeof(unsigned long long));

    k_clear<<<256, 256>>>();
    k_conv<<<dim3(5, 5, 32), dim3(16, 16)>>>(feat, conv_w, conv_b);
    k_heads<<<200, 128>>>(cls_w, cls_b, bbox_w, bbox_b);
    k_hist1<<<225, 1024>>>();
    k_scan1<<<1, 1024>>>();
    k_hist2<<<225, 1024>>>();
    k_scan2<<<1, 1024>>>();
    k_gather<<<225, 1024>>>();
    k_sort<<<1, 1024, GCAP * sizeof(unsigned long long)>>>();
    k_post<<<47, 128>>>();
    k_mask<<<dim3(94, 94), 64>>>();
    k_reduce<<<1, 128>>>();
    k_out<<<1, 128>>>(out);
}

// round 4
// speedup vs baseline: 1.0377x; 1.0257x over previous
#include <cuda_runtime.h>
#include <math.h>

#define GH 160
#define GW 160
#define NPIX (GH*GW)
#define CCH 256
#define NA 9
#define NANCH (NPIX*NA)
#define TOPK 6000
#define NW 94
#define POSTK 300
#define GCAP 8192
#define IMG 2560.0f
#define STRIDE 16
#define DWHC ((float)4.135166556742356)
#define NMS_THR 0.7f
#define MINSZ 16.0f
#define PADW 162
#define PADA (PADW*PADW)          // 26244

typedef unsigned long long u64;

// ---------- static scratch ----------
__device__ float  g_pad[CCH*PADA];            // zero-padded input
__device__ u64    g_wt[9*CCH*CCH];            // [tap][ci][co] duplicated (w,w)
__device__ float  g_feat[CCH*NPIX];
__device__ float4 g_boxes[NANCH];
__device__ float  g_scores[NANCH];
__device__ unsigned g_keys[NANCH];
__device__ unsigned g_h1[65536];
__device__ unsigned g_h2[65536];
__device__ unsigned g_B, g_above, g_thr, g_gcnt;
__device__ u64    g_gath[GCAP];
__device__ float4 g_tb[TOPK];
__device__ float  g_tarea[TOPK];
__device__ float  g_tsc[TOPK];
__device__ u64    g_valid[NW];
__device__ u64    g_mask[(size_t)TOPK*NW];
__device__ u64    g_remv[NW];

// ---------- f32x2 helpers ----------
__device__ __forceinline__ u64 pk2(float lo, float hi) {
    u64 r; asm("mov.b64 %0, {%1, %2};" : "=l"(r) : "f"(lo), "f"(hi)); return r;
}
__device__ __forceinline__ void upk2(u64 v, float& lo, float& hi) {
    asm("mov.b64 {%0, %1}, %2;" : "=f"(lo), "=f"(hi) : "l"(v));
}
__device__ __forceinline__ void ffma2(u64& c, u64 a, u64 b) {
    asm("fma.rn.f32x2 %0, %1, %2, %0;" : "+l"(c) : "l"(a), "l"(b));
}

// ---------- K0: clear ----------
__global__ void k_clear() {
    int i = blockIdx.x * 256 + threadIdx.x;
    if (i < 65536) { g_h1[i] = 0u; g_h2[i] = 0u; }
    if (i < NW) g_valid[i] = 0ull;
    if (i == 0) g_gcnt = 0u;
}

// ---------- prep: zero-pad input ----------
__global__ void k_pad(const float* __restrict__ feat) {
    int i = blockIdx.x * 256 + threadIdx.x;
    if (i >= CCH * PADA) return;
    int ci = i / PADA, rem = i % PADA;
    int y = rem / PADW, x = rem % PADW;
    float v = 0.f;
    if (y >= 1 && y <= GH && x >= 1 && x <= GW)
        v = feat[ci * NPIX + (y - 1) * GW + (x - 1)];
    g_pad[i] = v;
}

// ---------- prep: weight transpose + duplicate ----------
__global__ void k_wprep(const float* __restrict__ w) {
    int i = blockIdx.x * 256 + threadIdx.x;
    if (i >= 9 * CCH * CCH) return;
    int tap = i / (CCH*CCH), r = i % (CCH*CCH);
    int ci = r >> 8, co = r & 255;
    float v = w[(size_t)co * (CCH*9) + ci * 9 + tap];
    g_wt[i] = pk2(v, v);                       // i == (tap*256+ci)*256+co
}

// ---------- K1: conv as implicit GEMM (FFMA2) ----------
// block: 128 co x (2 rows x 32 cols) px, 256 threads, micro 8co x 4px
__global__ __launch_bounds__(256, 2)
void k_conv(const float* __restrict__ bias) {
    __shared__ u64 A2[2][8][128];              // [buf][k][co] dup pairs
    __shared__ u64 B2[2][8][2][16];            // [buf][k][r][c-pair]
    int tid = threadIdx.x;
    int cog = tid >> 4;                        // 0..15
    int pxg = tid & 15;
    int r   = pxg >> 3, c0 = (pxg & 7) * 4;
    int pt  = blockIdx.x;                      // 0..399
    int ty  = pt / 5, tx = pt % 5;
    int y0  = ty * 2, x0 = tx * 32;
    int co0 = blockIdx.y * 128;

    u64 acc[8][2];
#pragma unroll
    for (int u = 0; u < 8; u++) { acc[u][0] = 0ull; acc[u][1] = 0ull; }

    u64 a4[4]; float b2[2];

    auto loadCh = [&](int ch) {
        int tap = ch >> 5, ci0 = (ch & 31) << 3;
        int ky = tap / 3, kx = tap % 3;
#pragma unroll
        for (int q = 0; q < 4; q++) {
            int j = tid + q * 256;             // [k(8)][co(128)]
            int k = j >> 7, co = j & 127;
            a4[q] = g_wt[(size_t)(tap * 256 + ci0 + k) * 256 + co0 + co];
        }
#pragma unroll
        for (int q = 0; q < 2; q++) {
            int f = tid + q * 256;             // [k(8)][r(2)][c(32)]
            int k = f >> 6, rr = (f >> 5) & 1, cc = f & 31;
            b2[q] = g_pad[(size_t)(ci0 + k) * PADA + (y0 + rr + ky) * PADW + x0 + cc + kx];
        }
    };
    auto storeCh = [&](int buf) {
#pragma unroll
        for (int q = 0; q < 4; q++) {
            int j = tid + q * 256;
            A2[buf][j >> 7][j & 127] = a4[q];
        }
        float* bp = (float*)&B2[buf][0][0][0];
#pragma unroll
        for (int q = 0; q < 2; q++) bp[tid + q * 256] = b2[q];
    };

    loadCh(0);
    storeCh(0);
    for (int ch = 0; ch < 288; ch++) {
        __syncthreads();
        if (ch + 1 < 288) loadCh(ch + 1);
        int buf = ch & 1;
#pragma unroll
        for (int k = 0; k < 8; k++) {
            u64 b0 = B2[buf][k][r][(c0 >> 1) + 0];
            u64 b1 = B2[buf][k][r][(c0 >> 1) + 1];
#pragma unroll
            for (int u = 0; u < 8; u++) {
                u64 a = A2[buf][k][cog * 8 + u];
                ffma2(acc[u][0], b0, a);
                ffma2(acc[u][1], b1, a);
            }
        }
        if (ch + 1 < 288) storeCh((ch + 1) & 1);
    }

#pragma unroll
    for (int u = 0; u < 8; u++) {
        int co = co0 + cog * 8 + u;
        float bb = bias[co];
        float l0, h0, l1, h1;
        upk2(acc[u][0], l0, h0);
        upk2(acc[u][1], l1, h1);
        size_t o = (size_t)co * NPIX + (y0 + r) * GW + x0 + c0;
        g_feat[o + 0] = fmaxf(l0 + bb, 0.f);
        g_feat[o + 1] = fmaxf(h0 + bb, 0.f);
        g_feat[o + 2] = fmaxf(l1 + bb, 0.f);
        g_feat[o + 3] = fmaxf(h1 + bb, 0.f);
    }
}

// ---------- K2: heads + decode + sigmoid + key ----------
__global__ __launch_bounds__(128)
void k_heads(const float* __restrict__ cls_w, const float* __restrict__ cls_b,
             const float* __restrict__ bbox_w, const float* __restrict__ bbox_b) {
    __shared__ float ws[45][256];
    __shared__ float bs[45];
    int tid = threadIdx.x;
    for (int t = tid; t < 45*256; t += 128) {
        int j = t / 256, c = t % 256;
        ws[j][c] = (j < 9) ? cls_w[j*256 + c] : bbox_w[(j-9)*256 + c];
    }
    if (tid < 45) bs[tid] = (tid < 9) ? cls_b[tid] : bbox_b[tid - 9];
    __syncthreads();

    int pix = blockIdx.x * 128 + tid;
    float acc[45];
#pragma unroll
    for (int j = 0; j < 45; j++) acc[j] = 0.f;
    for (int c = 0; c < 256; c++) {
        float f = g_feat[c * NPIX + pix];
#pragma unroll
        for (int j = 0; j < 45; j++) acc[j] = fmaf(ws[j][c], f, acc[j]);
    }
#pragma unroll
    for (int j = 0; j < 45; j++) acc[j] += bs[j];

    int y = pix / GW, x = pix % GW;
    float fx = (float)(x * STRIDE), fy = (float)(y * STRIDE);
    const float ars[3] = {0.5f, 1.0f, 2.0f};
    const float scl[3] = {128.f, 256.f, 512.f};

#pragma unroll
    for (int a = 0; a < NA; a++) {
        int ai = a / 3, si = a % 3;
        float hr = sqrtf(ars[ai]);
        float wr = __fdiv_rn(1.0f, hr);
        float wsz = __fmul_rn(wr, scl[si]);
        float hsz = __fmul_rn(hr, scl[si]);
        float bx1 = rintf(__fmul_rn(-wsz, 0.5f));
        float bx2 = rintf(__fmul_rn( wsz, 0.5f));
        float by1 = rintf(__fmul_rn(-hsz, 0.5f));
        float by2 = rintf(__fmul_rn( hsz, 0.5f));
        float ax1 = __fadd_rn(fx, bx1), ax2 = __fadd_rn(fx, bx2);
        float ay1 = __fadd_rn(fy, by1), ay2 = __fadd_rn(fy, by2);
        float aw = __fsub_rn(ax2, ax1), ah = __fsub_rn(ay2, ay1);
        float cx = __fadd_rn(ax1, __fmul_rn(0.5f, aw));
        float cy = __fadd_rn(ay1, __fmul_rn(0.5f, ah));

        float score = __fdiv_rn(1.0f, __fadd_rn(1.0f, expf(-acc[a])));

        float dx = acc[9 + a*4 + 0];
        float dy = acc[9 + a*4 + 1];
        float dw = fminf(acc[9 + a*4 + 2], DWHC);
        float dh = fminf(acc[9 + a*4 + 3], DWHC);

        float pcx = __fadd_rn(__fmul_rn(dx, aw), cx);
        float pcy = __fadd_rn(__fmul_rn(dy, ah), cy);
        float pw  = __fmul_rn(expf(dw), aw);
        float ph  = __fmul_rn(expf(dh), ah);

        float x1 = __fsub_rn(pcx, __fmul_rn(0.5f, pw));
        float x2 = __fadd_rn(pcx, __fmul_rn(0.5f, pw));
        float y1 = __fsub_rn(pcy, __fmul_rn(0.5f, ph));
        float y2 = __fadd_rn(pcy, __fmul_rn(0.5f, ph));
        x1 = fminf(fmaxf(x1, 0.f), IMG);
        x2 = fminf(fmaxf(x2, 0.f), IMG);
        y1 = fminf(fmaxf(y1, 0.f), IMG);
        y2 = fminf(fmaxf(y2, 0.f), IMG);

        int idx = pix * NA + a;
        g_boxes[idx] = make_float4(x1, y1, x2, y2);
        g_scores[idx] = score;
        unsigned b = __float_as_uint(score);
        g_keys[idx] = b ^ ((b & 0x80000000u) ? 0xFFFFFFFFu : 0x80000000u);
    }
}

// ---------- radix select (warp-aggregated atomics) ----------
__global__ void k_hist1() {
    int i = blockIdx.x * 1024 + threadIdx.x;
    unsigned bkt = g_keys[i] >> 16;
    unsigned m = __match_any_sync(0xFFFFFFFFu, bkt);
    unsigned lane = threadIdx.x & 31;
    if (lane == (unsigned)(__ffs(m) - 1))
        atomicAdd(&g_h1[bkt], __popc(m));
}

__device__ __forceinline__ void scan_find(const unsigned* hist, unsigned base,
                                          unsigned* outB, unsigned* outAbove,
                                          int storeThr, unsigned thrHi) {
    __shared__ unsigned wsum[32];
    int t = threadIdx.x;
    int hi = 65535 - t * 64;
    unsigned s = 0;
    for (int k = 0; k < 64; k++) s += hist[hi - k];
    unsigned lane = t & 31, wid = t >> 5;
    unsigned incl = s;
#pragma unroll
    for (int d = 1; d < 32; d <<= 1) {
        unsigned v = __shfl_up_sync(0xFFFFFFFFu, incl, d);
        if (lane >= d) incl += v;
    }
    if (lane == 31) wsum[wid] = incl;
    __syncthreads();
    if (wid == 0) {
        unsigned v = wsum[lane], iv = v;
#pragma unroll
        for (int d = 1; d < 32; d <<= 1) {
            unsigned q = __shfl_up_sync(0xFFFFFFFFu, iv, d);
            if (lane >= d) iv += q;
        }
        wsum[lane] = iv - v;
    }
    __syncthreads();
    unsigned acc = incl - s + wsum[wid] + base;
    for (int k = 0; k < 64; k++) {
        unsigned b = hi - k, h = hist[b];
        if (acc < TOPK && acc + h >= TOPK) {
            if (storeThr) g_thr = (thrHi << 16) | b;
            else { *outB = b; *outAbove = acc; }
        }
        acc += h;
    }
}

__global__ void k_scan1() { scan_find(g_h1, 0, &g_B, &g_above, 0, 0); }

__global__ void k_hist2() {
    int i = blockIdx.x * 1024 + threadIdx.x;
    unsigned key = g_keys[i];
    bool c = (key >> 16) == g_B;
    unsigned act = __ballot_sync(0xFFFFFFFFu, c);
    if (c) {
        unsigned bkt = key & 0xFFFFu;
        unsigned m = __match_any_sync(act, bkt);
        if ((threadIdx.x & 31) == (unsigned)(__ffs(m) - 1))
            atomicAdd(&g_h2[bkt], __popc(m));
    }
}

__global__ void k_scan2() { scan_find(g_h2, g_above, 0, 0, 1, g_B); }

__global__ void k_gather() {
    __shared__ unsigned wcnt[32], wbase[32], bbase;
    int i = blockIdx.x * 1024 + threadIdx.x;
    unsigned key = g_keys[i];
    bool win = key >= g_thr;
    unsigned b = __ballot_sync(0xFFFFFFFFu, win);
    unsigned lane = threadIdx.x & 31, wid = threadIdx.x >> 5;
    if (lane == 0) wcnt[wid] = __popc(b);
    __syncthreads();
    if (threadIdx.x == 0) {
        unsigned tot = 0;
        for (int w = 0; w < 32; w++) { wbase[w] = tot; tot += wcnt[w]; }
        bbase = atomicAdd(&g_gcnt, tot);
    }
    __syncthreads();
    if (win) {
        unsigned pos = bbase + wbase[wid] + __popc(b & ((1u << lane) - 1u));
        if (pos < GCAP)
            g_gath[pos] = ((u64)key << 32) | (unsigned)(~i);
    }
}

// ---------- bitonic sort in shared memory ----------
__global__ void k_sort() {
    extern __shared__ u64 s[];
    int t = threadIdx.x;
    unsigned n = g_gcnt; if (n > GCAP) n = GCAP;
    for (int i = t; i < GCAP; i += 1024)
        s[i] = (i < (int)n) ? g_gath[i] : 0ull;
    __syncthreads();
    for (int k = 2; k <= GCAP; k <<= 1) {
        for (int j = k >> 1; j > 0; j >>= 1) {
            for (int p = t; p < GCAP/2; p += 1024) {
                int i = ((p / j) * 2 * j) + (p % j);
                int x = i + j;
                u64 a = s[i], b = s[x];
                bool desc = ((i & k) == 0);
                if ((a < b) == desc) { s[i] = b; s[x] = a; }
            }
            __syncthreads();
        }
    }
    for (int i = t; i < TOPK; i += 1024) g_gath[i] = s[i];
}

// ---------- unpack top-6000 ----------
__global__ void k_post() {
    int i = blockIdx.x * 128 + threadIdx.x;
    if (i >= TOPK) return;
    u64 kk = g_gath[i];
    unsigned idx = ~(unsigned)(kk & 0xFFFFFFFFull);
    float4 b = g_boxes[idx];
    g_tb[i] = b;
    float bw = __fsub_rn(b.z, b.x), bh = __fsub_rn(b.w, b.y);
    g_tarea[i] = __fmul_rn(bw, bh);
    g_tsc[i] = g_scores[idx];
    if (bw >= MINSZ && bh >= MINSZ)
        atomicOr(&g_valid[i >> 6], 1ull << (i & 63));
}

// ---------- NMS mask ----------
__global__ void k_mask() {
    int bi = blockIdx.y, bj = blockIdx.x;
    __shared__ float4 cb[64];
    __shared__ float  ca[64];
    int jb = bj * 64;
    int nc = min(64, TOPK - jb);
    int t = threadIdx.x;
    if (t < nc) { cb[t] = g_tb[jb + t]; ca[t] = g_tarea[jb + t]; }
    __syncthreads();
    int i = bi * 64 + t;
    if (i >= TOPK) return;
    u64 w = 0ull;
    if (bj >= bi) {
        float4 b = g_tb[i];
        float ai = g_tarea[i];
        for (int c = 0; c < nc; c++) {
            int j = jb + c;
            if (j <= i) continue;
            float4 o = cb[c];
            float xl = fmaxf(b.x, o.x), yt = fmaxf(b.y, o.y);
            float xr = fminf(b.z, o.z), yb = fminf(b.w, o.w);
            float iw = fmaxf(__fsub_rn(xr, xl), 0.f);
            float ih = fmaxf(__fsub_rn(yb, yt), 0.f);
            float inter = __fmul_rn(iw, ih);
            float iou = __fdiv_rn(inter, __fsub_rn(__fadd_rn(ai, ca[c]), inter));
            if (iou > NMS_THR) w |= 1ull << c;
        }
    }
    g_mask[(size_t)i * NW + bj] = w;
}

// ---------- NMS sequential reduce ----------
__global__ void k_reduce() {
    __shared__ u64 st[64][NW];
    __shared__ u64 remv[NW];
    __shared__ u64 cur;
    int t = threadIdx.x;
    if (t < NW) remv[t] = 0ull;
    __syncthreads();
    for (int cw = 0; cw < NW; cw++) {
        int base = cw * 64;
        int nr = min(64, TOPK - base);
        for (int idx = t; idx < nr * NW; idx += 128) {
            int r = idx / NW, wd = idx % NW;
            st[r][wd] = g_mask[(size_t)(base + r) * NW + wd];
        }
        __syncthreads();
        if (t == 0) {
            u64 rem = remv[cw] | ~g_valid[cw];
            for (int b = 0; b < nr; b++)
                if (!((rem >> b) & 1ull)) rem |= st[b][cw];
            remv[cw] = rem; cur = rem;
        }
        __syncthreads();
        u64 rem = cur;
        if (t < NW && t > cw) {
            u64 acc = remv[t];
            for (int b = 0; b < nr; b++)
                if (!((rem >> b) & 1ull)) acc |= st[b][t];
            remv[t] = acc;
        }
        __syncthreads();
    }
    if (t < NW) g_remv[t] = remv[t];
}

// ---------- emit top-300 ----------
__global__ void k_out(float* __restrict__ out) {
    __shared__ u64 keep[NW];
    __shared__ int ks[NW], ns[NW];
    __shared__ int Kc;
    int t = threadIdx.x;
    if (t < NW) {
        u64 k = ~g_remv[t];
        if (t == NW - 1) k &= (1ull << 48) - 1ull;
        keep[t] = k;
    }
    __syncthreads();
    if (t == 0) {
        int a = 0, b = 0;
        for (int w = 0; w < NW; w++) {
            ks[w] = a; ns[w] = b;
            int nb = (w == NW - 1) ? 48 : 64;
            int p = __popcll(keep[w]);
            a += p; b += nb - p;
        }
        Kc = min(a, POSTK);
    }
    __syncthreads();
    int kc = Kc;
    for (int i = t; i < TOPK; i += 128) {
        int w = i >> 6, b = i & 63;
        u64 kw = keep[w];
        u64 low = (b == 0) ? 0ull : (kw & ((1ull << b) - 1ull));
        bool isk = (kw >> b) & 1ull;
        if (isk) {
            int pos = ks[w] + __popcll(low);
            if (pos < POSTK) {
                float4 bb = g_tb[i];
                out[pos*5+0] = bb.x; out[pos*5+1] = bb.y;
                out[pos*5+2] = bb.z; out[pos*5+3] = bb.w;
                out[pos*5+4] = g_tsc[i];
            }
        } else {
            u64 nlow = (b == 0) ? 0ull : ((~kw) & ((1ull << b) - 1ull));
            int pos = kc + ns[w] + __popcll(nlow);
            if (pos < POSTK) {
                float4 bb = g_tb[i];
                out[pos*5+0] = bb.x; out[pos*5+1] = bb.y;
                out[pos*5+2] = bb.z; out[pos*5+3] = bb.w;
                out[pos*5+4] = -1.0f;
            }
        }
    }
}

extern "C" void kernel_launch(void* const* d_in, const int* in_sizes, int n_in,
                              void* d_out, int out_size) {
    const float* feat   = (const float*)d_in[0];
    const float* conv_w = (const float*)d_in[2];
    const float* conv_b = (const float*)d_in[3];
    const float* cls_w  = (const float*)d_in[4];
    const float* cls_b  = (const float*)d_in[5];
    const float* bbox_w = (const float*)d_in[6];
    const float* bbox_b = (const float*)d_in[7];
    float* out = (float*)d_out;

    cudaFuncSetAttribute(k_sort, cudaFuncAttributeMaxDynamicSharedMemorySize,
                         GCAP * sizeof(u64));

    k_clear<<<256, 256>>>();
    k_pad<<<(CCH*PADA + 255) / 256, 256>>>(feat);
    k_wprep<<<(9*CCH*CCH + 255) / 256, 256>>>(conv_w);
    k_conv<<<dim3(400, 2), 256>>>(conv_b);
    k_heads<<<200, 128>>>(cls_w, cls_b, bbox_w, bbox_b);
    k_hist1<<<225, 1024>>>();
    k_scan1<<<1, 1024>>>();
    k_hist2<<<225, 1024>>>();
    k_scan2<<<1, 1024>>>();
    k_gather<<<225, 1024>>>();
    k_sort<<<1, 1024, GCAP * sizeof(u64)>>>();
    k_post<<<47, 128>>>();
    k_mask<<<dim3(94, 94), 64>>>();
    k_reduce<<<1, 128>>>();
    k_out<<<1, 128>>>(out);
}

// round 5
// speedup vs baseline: 1.0570x; 1.0186x over previous
#include <cuda_runtime.h>
#include <math.h>

#define GH 160
#define GW 160
#define NPIX (GH*GW)
#define CCH 256
#define NA 9
#define NANCH (NPIX*NA)
#define TOPK 6000
#define NW 94
#define POSTK 300
#define GCAP 8192
#define IMG 2560.0f
#define STRIDE 16
#define DWHC ((float)4.135166556742356)
#define NMS_THR 0.7f
#define MINSZ 16.0f
#define PADW 162
#define PADA (PADW*PADW)

typedef unsigned long long u64;

// ---------- static scratch ----------
__device__ __align__(16) float  g_pad[CCH*PADA];
__device__ __align__(16) u64    g_wt[9*CCH*CCH];     // [tap][ci][co] dup (w,w)
__device__ __align__(16) float  g_feat[CCH*NPIX];
__device__ float4 g_boxes[NANCH];
__device__ float  g_scores[NANCH];
__device__ unsigned g_keys[NANCH];
__device__ unsigned g_h256[256];
__device__ unsigned g_pref, g_above2, g_thr, g_gcnt;
__device__ u64    g_gath[GCAP];
__device__ float4 g_tb[TOPK];
__device__ float  g_tarea[TOPK];
__device__ float  g_tsc[TOPK];
__device__ u64    g_valid[NW];
__device__ u64    g_mask[(size_t)TOPK*NW];
__device__ u64    g_remv[NW];

// ---------- f32x2 helpers ----------
__device__ __forceinline__ u64 pk2(float lo, float hi) {
    u64 r; asm("mov.b64 %0, {%1, %2};" : "=l"(r) : "f"(lo), "f"(hi)); return r;
}
__device__ __forceinline__ void upk2(u64 v, float& lo, float& hi) {
    asm("mov.b64 {%0, %1}, %2;" : "=f"(lo), "=f"(hi) : "l"(v));
}
__device__ __forceinline__ void ffma2(u64& c, u64 a, u64 b) {
    asm("fma.rn.f32x2 %0, %1, %2, %0;" : "+l"(c) : "l"(a), "l"(b));
}

// ---------- K0: clear ----------
__global__ void k_clear() {
    int i = threadIdx.x;
    if (i < 256) g_h256[i] = 0u;
    if (i < NW) g_valid[i] = 0ull;
    if (i == 0) { g_gcnt = 0u; g_pref = 0u; g_above2 = 0u; }
}

// ---------- prep: zero-pad ----------
__global__ void k_pad(const float* __restrict__ feat) {
    int i = blockIdx.x * 256 + threadIdx.x;
    if (i >= CCH * PADA) return;
    int ci = i / PADA, rem = i % PADA;
    int y = rem / PADW, x = rem % PADW;
    float v = 0.f;
    if (y >= 1 && y <= GH && x >= 1 && x <= GW)
        v = feat[ci * NPIX + (y - 1) * GW + (x - 1)];
    g_pad[i] = v;
}

// ---------- prep: weight transpose + dup ----------
__global__ void k_wprep(const float* __restrict__ w) {
    int i = blockIdx.x * 256 + threadIdx.x;
    if (i >= 9 * CCH * CCH) return;
    int tap = i / (CCH*CCH), r = i % (CCH*CCH);
    int ci = r >> 8, co = r & 255;
    float v = w[(size_t)co * (CCH*9) + ci * 9 + tap];
    g_wt[i] = pk2(v, v);
}

// ---------- K1: conv implicit GEMM, micro 8co x 8px, LDS.128 ----------
// block: 128 co x (4 rows x 32 cols), 256 threads
__global__ __launch_bounds__(256, 2)
void k_conv(const float* __restrict__ bias) {
    __shared__ __align__(16) u64   As[2][8][128];
    __shared__ __align__(16) float Bs[2][8][4][32];
    int tid = threadIdx.x;
    int cog = tid >> 4;                 // 0..15 -> 8 co each
    int pxg = tid & 15;
    int rr  = pxg >> 2;                 // 0..3
    int cc0 = (pxg & 3) * 8;            // 0,8,16,24
    int pt  = blockIdx.x;               // 0..199
    int ty  = pt / 5, tx = pt % 5;
    int y0  = ty * 4, x0 = tx * 32;
    int co0 = blockIdx.y * 128;

    u64 acc[8][4];
#pragma unroll
    for (int u = 0; u < 8; u++)
#pragma unroll
        for (int p = 0; p < 4; p++) acc[u][p] = 0ull;

    ulonglong2 pa[2]; float pb[4];

    auto loadCh = [&](int ch) {
        int tap = ch >> 5, ci0 = (ch & 31) << 3;
        int ky = tap / 3, kx = tap % 3;
#pragma unroll
        for (int q = 0; q < 2; q++) {
            int j = (tid + q * 256) * 2;       // u64 idx in [k(8)][co(128)]
            int k = j >> 7, co = j & 127;
            pa[q] = *(const ulonglong2*)&g_wt[(size_t)(tap * 256 + ci0 + k) * 256 + co0 + co];
        }
#pragma unroll
        for (int q = 0; q < 4; q++) {
            int f = tid + q * 256;             // [k(8)][r(4)][c(32)]
            int k = f >> 7, r2 = (f >> 5) & 3, cc = f & 31;
            pb[q] = g_pad[(size_t)(ci0 + k) * PADA + (y0 + r2 + ky) * PADW + x0 + cc + kx];
        }
    };
    auto storeCh = [&](int buf) {
#pragma unroll
        for (int q = 0; q < 2; q++) {
            int j = (tid + q * 256) * 2;
            int k = j >> 7, co = j & 127;
            *(ulonglong2*)&As[buf][k][co] = pa[q];
        }
        float* bp = &Bs[buf][0][0][0];
#pragma unroll
        for (int q = 0; q < 4; q++) bp[tid + q * 256] = pb[q];
    };

    loadCh(0);
    storeCh(0);
    for (int ch = 0; ch < 288; ch++) {
        __syncthreads();
        if (ch + 1 < 288) loadCh(ch + 1);
        int buf = ch & 1;
#pragma unroll
        for (int k = 0; k < 8; k++) {
            ulonglong2 bA = *(const ulonglong2*)&Bs[buf][k][rr][cc0];
            ulonglong2 bB = *(const ulonglong2*)&Bs[buf][k][rr][cc0 + 4];
#pragma unroll
            for (int uu = 0; uu < 4; uu++) {
                ulonglong2 a = *(const ulonglong2*)&As[buf][k][cog * 8 + uu * 2];
                ffma2(acc[uu*2+0][0], bA.x, a.x);
                ffma2(acc[uu*2+0][1], bA.y, a.x);
                ffma2(acc[uu*2+0][2], bB.x, a.x);
                ffma2(acc[uu*2+0][3], bB.y, a.x);
                ffma2(acc[uu*2+1][0], bA.x, a.y);
                ffma2(acc[uu*2+1][1], bA.y, a.y);
                ffma2(acc[uu*2+1][2], bB.x, a.y);
                ffma2(acc[uu*2+1][3], bB.y, a.y);
            }
        }
        if (ch + 1 < 288) storeCh((ch + 1) & 1);
    }

#pragma unroll
    for (int u = 0; u < 8; u++) {
        int co = co0 + cog * 8 + u;
        float bb = bias[co];
        float v[8];
#pragma unroll
        for (int p = 0; p < 4; p++) upk2(acc[u][p], v[2*p], v[2*p+1]);
#pragma unroll
        for (int q = 0; q < 8; q++) v[q] = fmaxf(v[q] + bb, 0.f);
        size_t o = (size_t)co * NPIX + (y0 + rr) * GW + x0 + cc0;
        *(float4*)&g_feat[o]     = make_float4(v[0], v[1], v[2], v[3]);
        *(float4*)&g_feat[o + 4] = make_float4(v[4], v[5], v[6], v[7]);
    }
}

// ---------- K2: heads + decode + sigmoid + key ----------
__global__ __launch_bounds__(128)
void k_heads(const float* __restrict__ cls_w, const float* __restrict__ cls_b,
             const float* __restrict__ bbox_w, const float* __restrict__ bbox_b) {
    __shared__ float ws[45][256];
    __shared__ float bs[45];
    int tid = threadIdx.x;
    for (int t = tid; t < 45*256; t += 128) {
        int j = t / 256, c = t % 256;
        ws[j][c] = (j < 9) ? cls_w[j*256 + c] : bbox_w[(j-9)*256 + c];
    }
    if (tid < 45) bs[tid] = (tid < 9) ? cls_b[tid] : bbox_b[tid - 9];
    __syncthreads();

    int pix = blockIdx.x * 128 + tid;
    float acc[45];
#pragma unroll
    for (int j = 0; j < 45; j++) acc[j] = 0.f;
    for (int c = 0; c < 256; c++) {
        float f = g_feat[c * NPIX + pix];
#pragma unroll
        for (int j = 0; j < 45; j++) acc[j] = fmaf(ws[j][c], f, acc[j]);
    }
#pragma unroll
    for (int j = 0; j < 45; j++) acc[j] += bs[j];

    int y = pix / GW, x = pix % GW;
    float fx = (float)(x * STRIDE), fy = (float)(y * STRIDE);
    const float ars[3] = {0.5f, 1.0f, 2.0f};
    const float scl[3] = {128.f, 256.f, 512.f};

#pragma unroll
    for (int a = 0; a < NA; a++) {
        int ai = a / 3, si = a % 3;
        float hr = sqrtf(ars[ai]);
        float wr = __fdiv_rn(1.0f, hr);
        float wsz = __fmul_rn(wr, scl[si]);
        float hsz = __fmul_rn(hr, scl[si]);
        float bx1 = rintf(__fmul_rn(-wsz, 0.5f));
        float bx2 = rintf(__fmul_rn( wsz, 0.5f));
        float by1 = rintf(__fmul_rn(-hsz, 0.5f));
        float by2 = rintf(__fmul_rn( hsz, 0.5f));
        float ax1 = __fadd_rn(fx, bx1), ax2 = __fadd_rn(fx, bx2);
        float ay1 = __fadd_rn(fy, by1), ay2 = __fadd_rn(fy, by2);
        float aw = __fsub_rn(ax2, ax1), ah = __fsub_rn(ay2, ay1);
        float cx = __fadd_rn(ax1, __fmul_rn(0.5f, aw));
        float cy = __fadd_rn(ay1, __fmul_rn(0.5f, ah));

        float score = __fdiv_rn(1.0f, __fadd_rn(1.0f, expf(-acc[a])));

        float dx = acc[9 + a*4 + 0];
        float dy = acc[9 + a*4 + 1];
        float dw = fminf(acc[9 + a*4 + 2], DWHC);
        float dh = fminf(acc[9 + a*4 + 3], DWHC);

        float pcx = __fadd_rn(__fmul_rn(dx, aw), cx);
        float pcy = __fadd_rn(__fmul_rn(dy, ah), cy);
        float pw  = __fmul_rn(expf(dw), aw);
        float ph  = __fmul_rn(expf(dh), ah);

        float x1 = __fsub_rn(pcx, __fmul_rn(0.5f, pw));
        float x2 = __fadd_rn(pcx, __fmul_rn(0.5f, pw));
        float y1 = __fsub_rn(pcy, __fmul_rn(0.5f, ph));
        float y2 = __fadd_rn(pcy, __fmul_rn(0.5f, ph));
        x1 = fminf(fmaxf(x1, 0.f), IMG);
        x2 = fminf(fmaxf(x2, 0.f), IMG);
        y1 = fminf(fmaxf(y1, 0.f), IMG);
        y2 = fminf(fmaxf(y2, 0.f), IMG);

        int idx = pix * NA + a;
        g_boxes[idx] = make_float4(x1, y1, x2, y2);
        g_scores[idx] = score;
        unsigned b = __float_as_uint(score);
        g_keys[idx] = b ^ ((b & 0x80000000u) ? 0xFFFFFFFFu : 0x80000000u);
    }
}

// ---------- radix select: 8-bit digit passes with smem histograms ----------
__global__ void k_hist8(int shift, unsigned pmask) {
    __shared__ unsigned sh[256];
    int t = threadIdx.x;
    for (int i = t; i < 256; i += 1024) sh[i] = 0;
    __syncthreads();
    int i = blockIdx.x * 1024 + t;
    unsigned key = g_keys[i];
    unsigned pref = g_pref;
    bool c = ((key & pmask) == (pref & pmask));
    unsigned act = __ballot_sync(0xFFFFFFFFu, c);
    if (c) {
        unsigned bin = (key >> shift) & 255u;
        unsigned m = __match_any_sync(act, bin);
        if ((t & 31) == (unsigned)(__ffs(m) - 1))
            atomicAdd(&sh[bin], __popc(m));
    }
    __syncthreads();
    for (int b = t; b < 256; b += 1024)
        if (sh[b]) atomicAdd(&g_h256[b], sh[b]);
}

__global__ void k_scan8(int shift, int last) {
    __shared__ unsigned bins[256];
    int t = threadIdx.x;
    bins[t] = g_h256[t];
    g_h256[t] = 0;                      // reset for next pass
    __syncthreads();
    if (t == 0) {
        unsigned acc = g_above2;
        for (int b = 255; b >= 0; b--) {
            unsigned h = bins[b];
            if (acc < TOPK && acc + h >= TOPK) {
                g_pref |= ((unsigned)b) << shift;
                g_above2 = acc;
                if (last) g_thr = g_pref;
                break;
            }
            acc += h;
        }
    }
}

__global__ void k_gather() {
    __shared__ unsigned wcnt[32], wbase[32], bbase;
    int i = blockIdx.x * 1024 + threadIdx.x;
    unsigned key = g_keys[i];
    bool win = key >= g_thr;
    unsigned b = __ballot_sync(0xFFFFFFFFu, win);
    unsigned lane = threadIdx.x & 31, wid = threadIdx.x >> 5;
    if (lane == 0) wcnt[wid] = __popc(b);
    __syncthreads();
    if (threadIdx.x == 0) {
        unsigned tot = 0;
        for (int w = 0; w < 32; w++) { wbase[w] = tot; tot += wcnt[w]; }
        bbase = atomicAdd(&g_gcnt, tot);
    }
    __syncthreads();
    if (win) {
        unsigned pos = bbase + wbase[wid] + __popc(b & ((1u << lane) - 1u));
        if (pos < GCAP)
            g_gath[pos] = ((u64)key << 32) | (unsigned)(~i);
    }
}

// ---------- bitonic sort in shared memory ----------
__global__ void k_sort() {
    extern __shared__ u64 s[];
    int t = threadIdx.x;
    unsigned n = g_gcnt; if (n > GCAP) n = GCAP;
    for (int i = t; i < GCAP; i += 1024)
        s[i] = (i < (int)n) ? g_gath[i] : 0ull;
    __syncthreads();
    for (int k = 2; k <= GCAP; k <<= 1) {
        for (int j = k >> 1; j > 0; j >>= 1) {
            for (int p = t; p < GCAP/2; p += 1024) {
                int i = ((p / j) * 2 * j) + (p % j);
                int x = i + j;
                u64 a = s[i], b = s[x];
                bool desc = ((i & k) == 0);
                if ((a < b) == desc) { s[i] = b; s[x] = a; }
            }
            __syncthreads();
        }
    }
    for (int i = t; i < TOPK; i += 1024) g_gath[i] = s[i];
}

// ---------- unpack top-6000 ----------
__global__ void k_post() {
    int i = blockIdx.x * 128 + threadIdx.x;
    if (i >= TOPK) return;
    u64 kk = g_gath[i];
    unsigned idx = ~(unsigned)(kk & 0xFFFFFFFFull);
    float4 b = g_boxes[idx];
    g_tb[i] = b;
    float bw = __fsub_rn(b.z, b.x), bh = __fsub_rn(b.w, b.y);
    g_tarea[i] = __fmul_rn(bw, bh);
    g_tsc[i] = g_scores[idx];
    if (bw >= MINSZ && bh >= MINSZ)
        atomicOr(&g_valid[i >> 6], 1ull << (i & 63));
}

// ---------- NMS mask ----------
__global__ void k_mask() {
    int bi = blockIdx.y, bj = blockIdx.x;
    __shared__ float4 cb[64];
    __shared__ float  ca[64];
    int jb = bj * 64;
    int nc = min(64, TOPK - jb);
    int t = threadIdx.x;
    if (t < nc) { cb[t] = g_tb[jb + t]; ca[t] = g_tarea[jb + t]; }
    __syncthreads();
    int i = bi * 64 + t;
    if (i >= TOPK) return;
    u64 w = 0ull;
    if (bj >= bi) {
        float4 b = g_tb[i];
        float ai = g_tarea[i];
        for (int c = 0; c < nc; c++) {
            int j = jb + c;
            if (j <= i) continue;
            float4 o = cb[c];
            float xl = fmaxf(b.x, o.x), yt = fmaxf(b.y, o.y);
            float xr = fminf(b.z, o.z), yb = fminf(b.w, o.w);
            float iw = fmaxf(__fsub_rn(xr, xl), 0.f);
            float ih = fmaxf(__fsub_rn(yb, yt), 0.f);
            float inter = __fmul_rn(iw, ih);
            float iou = __fdiv_rn(inter, __fsub_rn(__fadd_rn(ai, ca[c]), inter));
            if (iou > NMS_THR) w |= 1ull << c;
        }
    }
    g_mask[(size_t)i * NW + bj] = w;
}

// ---------- NMS sequential reduce (live-bit iteration) ----------
__global__ void k_reduce() {
    __shared__ u64 st[64][NW];
    __shared__ u64 remv[NW];
    __shared__ u64 curKept;
    int t = threadIdx.x;                 // 256 threads
    if (t < NW) remv[t] = 0ull;
    __syncthreads();
    for (int cw = 0; cw < NW; cw++) {
        int base = cw * 64;
        int nr = min(64, TOPK - base);
        for (int idx = t; idx < nr * NW; idx += 256) {
            int r = idx / NW, wd = idx % NW;
            st[r][wd] = g_mask[(size_t)(base + r) * NW + wd];
        }
        __syncthreads();
        if (t == 0) {
            u64 span = (nr == 64) ? ~0ull : ((1ull << nr) - 1ull);
            u64 rem = remv[cw] | ~g_valid[cw];
            u64 live = ~rem & span;
            while (live) {
                int b = __ffsll(live) - 1;
                rem |= st[b][cw];
                live &= live - 1;       // clear b
                live &= ~rem;           // clear newly suppressed
            }
            remv[cw] = rem;
            curKept = ~rem & span;
        }
        __syncthreads();
        u64 kept = curKept;
        if (t < NW && t > cw) {
            u64 a = remv[t], kk = kept;
            while (kk) {
                int b = __ffsll(kk) - 1;
                kk &= kk - 1;
                a |= st[b][t];
            }
            remv[t] = a;
        }
        __syncthreads();
    }
    if (t < NW) g_remv[t] = remv[t];
}

// ---------- emit top-300 ----------
__global__ void k_out(float* __restrict__ out) {
    __shared__ u64 keep[NW];
    __shared__ int ks[NW], ns[NW];
    __shared__ int Kc;
    int t = threadIdx.x;
    if (t < NW) {
        u64 k = ~g_remv[t];
        if (t == NW - 1) k &= (1ull << 48) - 1ull;
        keep[t] = k;
    }
    __syncthreads();
    if (t == 0) {
        int a = 0, b = 0;
        for (int w = 0; w < NW; w++) {
            ks[w] = a; ns[w] = b;
            int nb = (w == NW - 1) ? 48 : 64;
            int p = __popcll(keep[w]);
            a += p; b += nb - p;
        }
        Kc = min(a, POSTK);
    }
    __syncthreads();
    int kc = Kc;
    for (int i = t; i < TOPK; i += 128) {
        int w = i >> 6, b = i & 63;
        u64 kw = keep[w];
        u64 low = (b == 0) ? 0ull : (kw & ((1ull << b) - 1ull));
        bool isk = (kw >> b) & 1ull;
        if (isk) {
            int pos = ks[w] + __popcll(low);
            if (pos < POSTK) {
                float4 bb = g_tb[i];
                out[pos*5+0] = bb.x; out[pos*5+1] = bb.y;
                out[pos*5+2] = bb.z; out[pos*5+3] = bb.w;
                out[pos*5+4] = g_tsc[i];
            }
        } else {
            u64 nlow = (b == 0) ? 0ull : ((~kw) & ((1ull << b) - 1ull));
            int pos = kc + ns[w] + __popcll(nlow);
            if (pos < POSTK) {
                float4 bb = g_tb[i];
                out[pos*5+0] = bb.x; out[pos*5+1] = bb.y;
                out[pos*5+2] = bb.z; out[pos*5+3] = bb.w;
                out[pos*5+4] = -1.0f;
            }
        }
    }
}

extern "C" void kernel_launch(void* const* d_in, const int* in_sizes, int n_in,
                              void* d_out, int out_size) {
    const float* feat   = (const float*)d_in[0];
    const float* conv_w = (const float*)d_in[2];
    const float* conv_b = (const float*)d_in[3];
    const float* cls_w  = (const float*)d_in[4];
    const float* cls_b  = (const float*)d_in[5];
    const float* bbox_w = (const float*)d_in[6];
    const float* bbox_b = (const float*)d_in[7];
    float* out = (float*)d_out;

    cudaFuncSetAttribute(k_sort, cudaFuncAttributeMaxDynamicSharedMemorySize,
                         GCAP * sizeof(u64));

    k_clear<<<1, 256>>>();
    k_pad<<<(CCH*PADA + 255) / 256, 256>>>(feat);
    k_wprep<<<(9*CCH*CCH + 255) / 256, 256>>>(conv_w);
    k_conv<<<dim3(200, 2), 256>>>(conv_b);
    k_heads<<<200, 128>>>(cls_w, cls_b, bbox_w, bbox_b);
    k_hist8<<<225, 1024>>>(24, 0x00000000u);
    k_scan8<<<1, 256>>>(24, 0);
    k_hist8<<<225, 1024>>>(16, 0xFF000000u);
    k_scan8<<<1, 256>>>(16, 0);
    k_hist8<<<225, 1024>>>(8,  0xFFFF0000u);
    k_scan8<<<1, 256>>>(8, 0);
    k_hist8<<<225, 1024>>>(0,  0xFFFFFF00u);
    k_scan8<<<1, 256>>>(0, 1);
    k_gather<<<225, 1024>>>();
    k_sort<<<1, 1024, GCAP * sizeof(u64)>>>();
    k_post<<<47, 128>>>();
    k_mask<<<dim3(94, 94), 64>>>();
    k_reduce<<<1, 256>>>();
    k_out<<<1, 128>>>(out);
}